// round 14
// baseline (speedup 1.0000x reference)
#include <cuda_runtime.h>
#include <cuda_fp16.h>

#define DIM 64
#define DIM2 (DIM / 2)
#define N_LAYERS 3
#define NODES_MAX 262144
#define EDGES_MAX 16000000
#define CAP 96             // bucket capacity (mean degree guard: <=80)
#define OVF_MAX 1048576
#define SCAN_BLK 1024
#define PARTS_MAX 256      // NODES_MAX / SCAN_BLK
#define VQ_BITS 14
#define VQ_SCALE 16384.0f
#define VQ_MASK 0x3FFFu

// -------- static device scratch (no allocations allowed) --------
// Referenced ONLY from device code (host-side symbol decay = ATS-backed
// host shadow on GB300 — the silent R2-R4 bug).
__device__ int          g_is64;
__device__ int          g_ovf_n;
__device__ int          g_list_n;
__device__ int          g_counts [NODES_MAX];
__device__ int          g_part   [PARTS_MAX];
__device__ int          g_offsets[NODES_MAX + 1];
__device__ int          g_cursor [NODES_MAX];
__device__ int          g_flag   [NODES_MAX];
__device__ int          g_list   [NODES_MAX];          // unique queried nodes
__device__ int2         g_csr    [EDGES_MAX];          // fallback CSR (exact)
__device__ unsigned int g_bucket [(size_t)NODES_MAX * CAP];  // packed (src<<14)|q
__device__ int4         g_ovf    [OVF_MAX];            // exact (src, dst, val_bits)
__device__ __half2      h_bufA   [NODES_MAX * DIM2];   // e0 -> layer-2 output
__device__ __half2      h_bufB   [NODES_MAX * DIM2];   // layer-1 output
__device__ float        g_l3     [NODES_MAX * DIM];    // layer-3 output (flagged)

// -------- index loads: int32 or int64 --------
__device__ __forceinline__ int load_idx(const void* p, int i, bool is64) {
    if (is64) return (int)((const long long*)p)[i];
    return ((const int*)p)[i];
}
__device__ __forceinline__ int4 load_idx4(const void* p, int q, bool is64) {
    if (is64) {
        longlong2 a = ((const longlong2*)p)[2 * q];
        longlong2 b = ((const longlong2*)p)[2 * q + 1];
        return make_int4((int)a.x, (int)a.y, (int)b.x, (int)b.y);
    }
    return ((const int4*)p)[q];
}

// -------- dtype detection: odd 32-bit words all zero => int64 --------
__global__ void detect_kernel(const unsigned int* __restrict__ p, int nslots) {
    __shared__ unsigned int acc;
    if (threadIdx.x == 0) acc = 0u;
    __syncthreads();
    unsigned int v = 0u;
    for (int s = threadIdx.x; s < nslots; s += 1024) v |= p[2 * s + 1];
    if (v) atomicOr(&acc, 1u);
    __syncthreads();
    if (threadIdx.x == 0) g_is64 = (acc == 0u) ? 1 : 0;
}

// -------- init: h_bufA = fp16(emb); counts = flag = 0 --------
__global__ void init_kernel(const float* __restrict__ ue, const float* __restrict__ ie,
                            int nU2, int nT2, int n_nodes) {
    int i = blockIdx.x * blockDim.x + threadIdx.x;
    if (i == 0) { g_ovf_n = 0; g_list_n = 0; }
    if (i < nT2) {
        float2 v = (i < nU2) ? ((const float2*)ue)[i] : ((const float2*)ie)[i - nU2];
        h_bufA[i] = __floats2half2_rn(v.x, v.y);
    }
    if (i < n_nodes) { g_counts[i] = 0; g_flag[i] = 0; }
}

// -------- flag queried nodes + build dedup'd list --------
__global__ void flag_kernel(const void* __restrict__ users, const void* __restrict__ items,
                            int B, int n_users) {
    const bool is64 = (g_is64 != 0);
    int i = blockIdx.x * blockDim.x + threadIdx.x;
    if (i < B) {
        int u = load_idx(users, i, is64);
        if (atomicExch(&g_flag[u], 1) == 0) g_list[atomicAdd(&g_list_n, 1)] = u;
        int t = n_users + load_idx(items, i, is64);
        if (atomicExch(&g_flag[t], 1) == 0) g_list[atomicAdd(&g_list_n, 1)] = t;
    }
}

// ======== PRIMARY PATH: single-pass packed bucket fill with overflow ========
__device__ __forceinline__ void bucket_put(int d, int s, float v) {
    int pos = atomicAdd(&g_counts[d], 1);
    if (pos < CAP) {
        int q = __float2int_rn(v * VQ_SCALE);
        if (q > (int)VQ_MASK) q = VQ_MASK;
        if (q < 0) q = 0;
        g_bucket[(size_t)d * CAP + pos] = ((unsigned int)s << VQ_BITS) | (unsigned int)q;
    } else {
        int o = atomicAdd(&g_ovf_n, 1);
        if (o < OVF_MAX) g_ovf[o] = make_int4(s, d, __float_as_int(v), 0);
    }
}

__global__ void fill_bucket_kernel(const void* __restrict__ src, const void* __restrict__ dst,
                                   const float* __restrict__ val, int n_edges) {
    const bool is64 = (g_is64 != 0);
    int nq = n_edges >> 2;
    int stride = gridDim.x * blockDim.x;
    int tid0 = blockIdx.x * blockDim.x + threadIdx.x;
    for (int q = tid0; q < nq; q += stride) {
        int4   d = load_idx4(dst, q, is64);
        int4   s = load_idx4(src, q, is64);
        float4 v = ((const float4*)val)[q];
        bucket_put(d.x, s.x, v.x);
        bucket_put(d.y, s.y, v.y);
        bucket_put(d.z, s.z, v.z);
        bucket_put(d.w, s.w, v.w);
    }
    int t0 = nq << 2;
    int r = n_edges - t0;
    if (tid0 < r) {
        int e = t0 + tid0;
        bucket_put(load_idx(dst, e, is64), load_idx(src, e, is64), val[e]);
    }
}

// Overflow fix-up (exact) for layers 1-2: y[d] += v * x[s]. One warp/edge.
__global__ void ovf_add_kernel(int sel) {
    const __half2* __restrict__ x = sel ? h_bufB : h_bufA;
    __half2*       __restrict__ y = sel ? h_bufA : h_bufB;
    int n = g_ovf_n; if (n > OVF_MAX) n = OVF_MAX;
    int nw = (gridDim.x * blockDim.x) >> 5;
    int w  = (blockIdx.x * blockDim.x + threadIdx.x) >> 5;
    int lane = threadIdx.x & 31;
    for (int i = w; i < n; i += nw) {
        int4 e = g_ovf[i];
        float v = __int_as_float(e.z);
        float2 xf = __half22float2(x[(size_t)e.x * DIM2 + lane]);
        atomicAdd(&y[(size_t)e.y * DIM2 + lane], __floats2half2_rn(v * xf.x, v * xf.y));
    }
}

__global__ void ovf_add_l3_kernel() {
    int n = g_ovf_n; if (n > OVF_MAX) n = OVF_MAX;
    int nw = (gridDim.x * blockDim.x) >> 5;
    int w  = (blockIdx.x * blockDim.x + threadIdx.x) >> 5;
    int lane = threadIdx.x & 31;
    for (int i = w; i < n; i += nw) {
        int4 e = g_ovf[i];
        if (!g_flag[e.y]) continue;
        float v = __int_as_float(e.z);
        float2 xf = __half22float2(h_bufA[(size_t)e.x * DIM2 + lane]);
        float* yp = g_l3 + (size_t)e.y * DIM + lane * 2;
        atomicAdd(yp,     v * xf.x);
        atomicAdd(yp + 1, v * xf.y);
    }
}

// ======== FALLBACK PATH (exact int2 CSR): hist + scan + cursor fill ========
__global__ void hist_kernel(const void* __restrict__ dst, int n_edges) {
    const bool is64 = (g_is64 != 0);
    int nq = n_edges >> 2;
    int stride = gridDim.x * blockDim.x;
    int tid0 = blockIdx.x * blockDim.x + threadIdx.x;
    for (int q = tid0; q < nq; q += stride) {
        int4 d = load_idx4(dst, q, is64);
        atomicAdd(&g_counts[d.x], 1);
        atomicAdd(&g_counts[d.y], 1);
        atomicAdd(&g_counts[d.z], 1);
        atomicAdd(&g_counts[d.w], 1);
    }
    int t0 = nq << 2;
    int r = n_edges - t0;
    if (tid0 < r) atomicAdd(&g_counts[load_idx(dst, t0 + tid0, is64)], 1);
}

__global__ void __launch_bounds__(SCAN_BLK)
scan_blocks_kernel(int n_nodes) {
    __shared__ int warp_tot[32];
    int tid  = threadIdx.x;
    int lane = tid & 31, wid = tid >> 5;
    int i = blockIdx.x * SCAN_BLK + tid;
    int v = (i < n_nodes) ? g_counts[i] : 0;
    int x = v;
    #pragma unroll
    for (int o = 1; o < 32; o <<= 1) {
        int t = __shfl_up_sync(0xffffffffu, x, o);
        if (lane >= o) x += t;
    }
    if (lane == 31) warp_tot[wid] = x;
    __syncthreads();
    if (wid == 0) {
        int w = warp_tot[lane];
        #pragma unroll
        for (int o = 1; o < 32; o <<= 1) {
            int t = __shfl_up_sync(0xffffffffu, w, o);
            if (lane >= o) w += t;
        }
        warp_tot[lane] = w;
    }
    __syncthreads();
    int base = wid ? warp_tot[wid - 1] : 0;
    int incl = base + x;
    if (i < n_nodes) g_counts[i] = incl - v;
    if (tid == SCAN_BLK - 1) g_part[blockIdx.x] = incl;
}

__global__ void __launch_bounds__(PARTS_MAX)
scan_parts_kernel(int nb, int n_nodes) {
    __shared__ int warp_tot[8];
    int tid = threadIdx.x, lane = tid & 31, wid = tid >> 5;
    int v = (tid < nb) ? g_part[tid] : 0;
    int x = v;
    #pragma unroll
    for (int o = 1; o < 32; o <<= 1) {
        int t = __shfl_up_sync(0xffffffffu, x, o);
        if (lane >= o) x += t;
    }
    if (lane == 31) warp_tot[wid] = x;
    __syncthreads();
    if (wid == 0 && lane < 8) {
        int w = warp_tot[lane];
        #pragma unroll
        for (int o = 1; o < 8; o <<= 1) {
            int t = __shfl_up_sync(0xffu, w, o);
            if (lane >= o) w += t;
        }
        warp_tot[lane] = w;
    }
    __syncthreads();
    int base = wid ? warp_tot[wid - 1] : 0;
    int incl = base + x;
    if (tid < nb) g_part[tid] = incl - v;
    if (tid == PARTS_MAX - 1) g_offsets[n_nodes] = incl;
}

__global__ void __launch_bounds__(SCAN_BLK)
scan_add_kernel(int n_nodes) {
    int i = blockIdx.x * SCAN_BLK + threadIdx.x;
    if (i < n_nodes) {
        int o = g_counts[i] + g_part[blockIdx.x];
        g_offsets[i] = o;
        g_cursor [i] = o;
    }
}

__global__ void fill_kernel(const void* __restrict__ src, const void* __restrict__ dst,
                            const float* __restrict__ val, int n_edges) {
    const bool is64 = (g_is64 != 0);
    int nq = n_edges >> 2;
    int stride = gridDim.x * blockDim.x;
    int tid0 = blockIdx.x * blockDim.x + threadIdx.x;
    for (int q = tid0; q < nq; q += stride) {
        int4   d = load_idx4(dst, q, is64);
        int4   s = load_idx4(src, q, is64);
        float4 v = ((const float4*)val)[q];
        int p0 = atomicAdd(&g_cursor[d.x], 1);
        int p1 = atomicAdd(&g_cursor[d.y], 1);
        int p2 = atomicAdd(&g_cursor[d.z], 1);
        int p3 = atomicAdd(&g_cursor[d.w], 1);
        g_csr[p0] = make_int2(s.x, __float_as_int(v.x));
        g_csr[p1] = make_int2(s.y, __float_as_int(v.y));
        g_csr[p2] = make_int2(s.z, __float_as_int(v.z));
        g_csr[p3] = make_int2(s.w, __float_as_int(v.w));
    }
    int t0 = nq << 2;
    int r = n_edges - t0;
    if (tid0 < r) {
        int e = t0 + tid0;
        int d = load_idx(dst, e, is64);
        int pos = atomicAdd(&g_cursor[d], 1);
        g_csr[pos] = make_int2(load_idx(src, e, is64), __float_as_int(val[e]));
    }
}

// -------- SpMM bodies --------
// Packed: one shfl/edge, integer-valued weights, final x(1/16384) scale.
__device__ __forceinline__ float2 spmm_row_packed(const unsigned int* __restrict__ eb, int cnt,
                                                  const __half2* __restrict__ x, int lane) {
    float2 s0 = make_float2(0.f, 0.f), s1 = make_float2(0.f, 0.f);
    int e = 0;
    for (; e + 32 <= cnt; e += 32) {
        unsigned int ev = eb[e + lane];
        #pragma unroll
        for (int k = 0; k < 32; k += 2) {
            unsigned int wA = __shfl_sync(0xffffffffu, ev, k);
            unsigned int wB = __shfl_sync(0xffffffffu, ev, k + 1);
            float qA = (float)(wA & VQ_MASK);
            float qB = (float)(wB & VQ_MASK);
            float2 xa = __half22float2(x[(wA >> VQ_BITS) * DIM2 + lane]);
            float2 xb = __half22float2(x[(wB >> VQ_BITS) * DIM2 + lane]);
            s0.x += qA * xa.x; s0.y += qA * xa.y;
            s1.x += qB * xb.x; s1.y += qB * xb.y;
        }
    }
    int n = cnt - e;
    if (n > 0) {
        unsigned int ev = (lane < n) ? eb[e + lane] : 0u;
        for (int k = 0; k < n; k++) {
            unsigned int wN = __shfl_sync(0xffffffffu, ev, k);
            float qN = (float)(wN & VQ_MASK);
            float2 xf = __half22float2(x[(wN >> VQ_BITS) * DIM2 + lane]);
            if (k & 1) { s1.x += qN * xf.x; s1.y += qN * xf.y; }
            else       { s0.x += qN * xf.x; s0.y += qN * xf.y; }
        }
    }
    return make_float2((s0.x + s1.x) * (1.0f / VQ_SCALE),
                       (s0.y + s1.y) * (1.0f / VQ_SCALE));
}

// Exact int2 body (fallback CSR)
__device__ __forceinline__ float2 spmm_row_int2(const int2* __restrict__ eb, int cnt,
                                                const __half2* __restrict__ x, int lane) {
    float2 s0 = make_float2(0.f, 0.f), s1 = make_float2(0.f, 0.f);
    int e = 0;
    for (; e + 32 <= cnt; e += 32) {
        int2 ev = eb[e + lane];
        #pragma unroll
        for (int k = 0; k < 32; k += 2) {
            int   sA = __shfl_sync(0xffffffffu, ev.x, k);
            float vA = __int_as_float(__shfl_sync(0xffffffffu, ev.y, k));
            int   sB = __shfl_sync(0xffffffffu, ev.x, k + 1);
            float vB = __int_as_float(__shfl_sync(0xffffffffu, ev.y, k + 1));
            float2 xa = __half22float2(x[sA * DIM2 + lane]);
            float2 xb = __half22float2(x[sB * DIM2 + lane]);
            s0.x += vA * xa.x; s0.y += vA * xa.y;
            s1.x += vB * xb.x; s1.y += vB * xb.y;
        }
    }
    int n = cnt - e;
    if (n > 0) {
        int2 ev = (lane < n) ? eb[e + lane] : make_int2(0, 0);
        for (int k = 0; k < n; k++) {
            int   sN = __shfl_sync(0xffffffffu, ev.x, k);
            float vN = __int_as_float(__shfl_sync(0xffffffffu, ev.y, k));
            float2 xf = __half22float2(x[sN * DIM2 + lane]);
            if (k & 1) { s1.x += vN * xf.x; s1.y += vN * xf.y; }
            else       { s0.x += vN * xf.x; s0.y += vN * xf.y; }
        }
    }
    return make_float2(s0.x + s1.x, s0.y + s1.y);
}

__device__ __forceinline__ float2 spmm_node(int node, int use_bucket,
                                            const __half2* __restrict__ x, int lane) {
    if (use_bucket) {
        int c = g_counts[node];
        if (c > CAP) c = CAP;
        return spmm_row_packed(&g_bucket[(size_t)node * CAP], c, x, lane);
    }
    int beg = g_offsets[node];
    return spmm_row_int2(&g_csr[beg], g_offsets[node + 1] - beg, x, lane);
}

// Layers 1-2: full graph, fp16 -> fp16. sel=0: A->B, sel=1: B->A.
__global__ void __launch_bounds__(256)
spmm_full_kernel(int sel, int use_bucket, int n_nodes) {
    const __half2* __restrict__ x = sel ? h_bufB : h_bufA;
    __half2*       __restrict__ y = sel ? h_bufA : h_bufB;
    int warp = (blockIdx.x * blockDim.x + threadIdx.x) >> 5;
    int lane = threadIdx.x & 31;
    if (warp >= n_nodes) return;
    float2 s = spmm_node(warp, use_bucket, x, lane);
    y[(size_t)warp * DIM2 + lane] = __floats2half2_rn(s.x, s.y);
}

// Layer 3: compacted queried-node list only, fp16 -> fp32 g_l3.
__global__ void __launch_bounds__(256)
spmm_last_kernel(int use_bucket) {
    int w = (blockIdx.x * blockDim.x + threadIdx.x) >> 5;
    int lane = threadIdx.x & 31;
    if (w >= g_list_n) return;
    int node = g_list[w];
    float2 s = spmm_node(node, use_bucket, h_bufA, lane);
    ((float2*)(g_l3 + (size_t)node * DIM))[lane] = s;
}

// -------- final dot: acc = e0(inputs) + l1(bufB) + l2(bufA) + l3(g_l3) -------
__global__ void dot_kernel(const void* __restrict__ users, const void* __restrict__ items,
                           const float* __restrict__ ue, const float* __restrict__ ie,
                           float* __restrict__ out, int B, int n_users) {
    const bool is64 = (g_is64 != 0);
    int warp = (blockIdx.x * blockDim.x + threadIdx.x) >> 5;
    int lane = threadIdx.x & 31;
    if (warp >= B) return;
    int u  = load_idx(users, warp, is64);
    int ni = n_users + load_idx(items, warp, is64);

    float2 e0u = ((const float2*)ue)[(size_t)u * DIM2 + lane];
    float2 l1u = __half22float2(h_bufB[(size_t)u * DIM2 + lane]);
    float2 l2u = __half22float2(h_bufA[(size_t)u * DIM2 + lane]);
    float2 l3u = ((const float2*)(g_l3 + (size_t)u * DIM))[lane];
    float ax = e0u.x + l1u.x + l2u.x + l3u.x;
    float ay = e0u.y + l1u.y + l2u.y + l3u.y;

    float2 e0i = ((const float2*)ie)[(size_t)(ni - n_users) * DIM2 + lane];
    float2 l1i = __half22float2(h_bufB[(size_t)ni * DIM2 + lane]);
    float2 l2i = __half22float2(h_bufA[(size_t)ni * DIM2 + lane]);
    float2 l3i = ((const float2*)(g_l3 + (size_t)ni * DIM))[lane];
    float bx = e0i.x + l1i.x + l2i.x + l3i.x;
    float by = e0i.y + l1i.y + l2i.y + l3i.y;

    float p = ax * bx + ay * by;
    #pragma unroll
    for (int off = 16; off > 0; off >>= 1)
        p += __shfl_xor_sync(0xffffffffu, p, off);
    if (lane == 0) out[warp] = p * (1.0f / ((N_LAYERS + 1) * (N_LAYERS + 1)));
}

extern "C" void kernel_launch(void* const* d_in, const int* in_sizes, int n_in,
                              void* d_out, int out_size) {
    // ---- resolve input permutation from size fingerprint ----
    int iu, ii, is, id, iv, iue, iie;
    if ((long long)in_sizes[0] < (long long)in_sizes[2]) {
        iu = 0; ii = 1; is = 2; id = 3; iv = 4; iue = 5; iie = 6;   // dict order
    } else {
        id = 0; is = 1; iv = 2; iie = 3; ii = 4; iue = 5; iu = 6;   // alphabetical
    }
    const void*  users    = d_in[iu];
    const void*  items    = d_in[ii];
    const void*  edge_src = d_in[is];
    const void*  edge_dst = d_in[id];
    const float* edge_val = (const float*)d_in[iv];
    const float* user_emb = (const float*)d_in[iue];
    const float* item_emb = (const float*)d_in[iie];
    float* out = (float*)d_out;

    const int B       = in_sizes[iu];
    const int n_edges = in_sizes[is];
    const int n_users = in_sizes[iue] / DIM;
    const int n_items = in_sizes[iie] / DIM;
    const int n_nodes = n_users + n_items;
    const int nU2 = n_users * DIM / 2;
    const int nT2 = n_nodes * DIM / 2;
    const int nb  = (n_nodes + SCAN_BLK - 1) / SCAN_BLK;   // <= PARTS_MAX

    const int use_bucket = ((long long)n_edges <= 80LL * n_nodes) ? 1 : 0;

    int nslots = n_edges / 2 < 4096 ? n_edges / 2 : 4096;
    detect_kernel<<<1, 1024>>>((const unsigned int*)edge_src, nslots);
    init_kernel<<<(nT2 + 255) / 256, 256>>>(user_emb, item_emb, nU2, nT2, n_nodes);
    flag_kernel<<<(B + 255) / 256, 256>>>(users, items, B, n_users);

    if (use_bucket) {
        fill_bucket_kernel<<<2048, 256>>>(edge_src, edge_dst, edge_val, n_edges);
    } else {
        hist_kernel<<<2048, 256>>>(edge_dst, n_edges);
        scan_blocks_kernel<<<nb, SCAN_BLK>>>(n_nodes);
        scan_parts_kernel<<<1, PARTS_MAX>>>(nb, n_nodes);
        scan_add_kernel<<<nb, SCAN_BLK>>>(n_nodes);
        fill_kernel<<<2048, 256>>>(edge_src, edge_dst, edge_val, n_edges);
    }

    // propagation: layers 1-2 full, layer 3 only queried nodes (compact list)
    int spmm_grid = (n_nodes * 32 + 255) / 256;
    int l3_grid   = (2 * B * 32 + 255) / 256;   // covers worst-case list size 2B
    spmm_full_kernel<<<spmm_grid, 256>>>(0, use_bucket, n_nodes);   // l1: A -> B
    if (use_bucket) ovf_add_kernel<<<16, 256>>>(0);
    spmm_full_kernel<<<spmm_grid, 256>>>(1, use_bucket, n_nodes);   // l2: B -> A
    if (use_bucket) ovf_add_kernel<<<16, 256>>>(1);
    spmm_last_kernel<<<l3_grid, 256>>>(use_bucket);                 // l3: A -> g_l3
    if (use_bucket) ovf_add_l3_kernel<<<16, 256>>>();

    // final dots (acc assembled in-kernel)
    dot_kernel<<<(B * 32 + 255) / 256, 256>>>(users, items, user_emb, item_emb,
                                              out, B, n_users);
}

// round 15
// speedup vs baseline: 1.1186x; 1.1186x over previous
#include <cuda_runtime.h>
#include <cuda_fp16.h>

#define DIM 64
#define DIM2 (DIM / 2)
#define N_LAYERS 3
#define NODES_MAX 262144
#define EDGES_MAX 16000000
#define CAP 96             // bucket capacity (mean degree guard: <=80)
#define OVF_MAX 1048576
#define SCAN_BLK 1024
#define PARTS_MAX 256      // NODES_MAX / SCAN_BLK

// -------- static device scratch (no allocations allowed) --------
// Referenced ONLY from device code (host-side symbol decay = ATS-backed
// host shadow on GB300 — the silent R2-R4 bug).
__device__ int     g_is64;
__device__ int     g_ovf_n;
__device__ int     g_list_n;
__device__ int     g_counts [NODES_MAX];
__device__ int     g_part   [PARTS_MAX];
__device__ int     g_offsets[NODES_MAX + 1];
__device__ int     g_cursor [NODES_MAX];
__device__ int     g_flag   [NODES_MAX];
__device__ int     g_list   [NODES_MAX];            // unique queried nodes
__device__ int2    g_csr    [EDGES_MAX];            // fallback CSR (exact)
__device__ int2    g_bucket [(size_t)NODES_MAX * CAP];  // primary: int2 bucket CSR
__device__ int4    g_ovf    [OVF_MAX];              // exact (src, dst, val_bits)
__device__ __half2 h_bufA   [NODES_MAX * DIM2];     // e0 -> layer-2 output
__device__ __half2 h_bufB   [NODES_MAX * DIM2];     // layer-1 output
__device__ float   g_l3     [NODES_MAX * DIM];      // layer-3 output (queried rows)

// -------- index loads: int32 or int64 --------
__device__ __forceinline__ int load_idx(const void* p, int i, bool is64) {
    if (is64) return (int)((const long long*)p)[i];
    return ((const int*)p)[i];
}
__device__ __forceinline__ int4 load_idx4(const void* p, int q, bool is64) {
    if (is64) {
        longlong2 a = ((const longlong2*)p)[2 * q];
        longlong2 b = ((const longlong2*)p)[2 * q + 1];
        return make_int4((int)a.x, (int)a.y, (int)b.x, (int)b.y);
    }
    return ((const int4*)p)[q];
}

// -------- dtype detection: odd 32-bit words all zero => int64 --------
__global__ void detect_kernel(const unsigned int* __restrict__ p, int nslots) {
    __shared__ unsigned int acc;
    if (threadIdx.x == 0) acc = 0u;
    __syncthreads();
    unsigned int v = 0u;
    for (int s = threadIdx.x; s < nslots; s += 1024) v |= p[2 * s + 1];
    if (v) atomicOr(&acc, 1u);
    __syncthreads();
    if (threadIdx.x == 0) g_is64 = (acc == 0u) ? 1 : 0;
}

// -------- init: h_bufA = fp16(emb); counts = flag = 0 --------
__global__ void init_kernel(const float* __restrict__ ue, const float* __restrict__ ie,
                            int nU2, int nT2, int n_nodes) {
    int i = blockIdx.x * blockDim.x + threadIdx.x;
    if (i == 0) { g_ovf_n = 0; g_list_n = 0; }
    if (i < nT2) {
        float2 v = (i < nU2) ? ((const float2*)ue)[i] : ((const float2*)ie)[i - nU2];
        h_bufA[i] = __floats2half2_rn(v.x, v.y);
    }
    if (i < n_nodes) { g_counts[i] = 0; g_flag[i] = 0; }
}

// -------- flag queried nodes + build dedup'd list --------
__global__ void flag_kernel(const void* __restrict__ users, const void* __restrict__ items,
                            int B, int n_users) {
    const bool is64 = (g_is64 != 0);
    int i = blockIdx.x * blockDim.x + threadIdx.x;
    if (i < B) {
        int u = load_idx(users, i, is64);
        if (atomicExch(&g_flag[u], 1) == 0) g_list[atomicAdd(&g_list_n, 1)] = u;
        int t = n_users + load_idx(items, i, is64);
        if (atomicExch(&g_flag[t], 1) == 0) g_list[atomicAdd(&g_list_n, 1)] = t;
    }
}

// ======== PRIMARY PATH: single-pass int2 bucket fill with overflow ========
__device__ __forceinline__ void bucket_put(int d, int s, int vbits) {
    int pos = atomicAdd(&g_counts[d], 1);
    if (pos < CAP) {
        g_bucket[(size_t)d * CAP + pos] = make_int2(s, vbits);
    } else {
        int o = atomicAdd(&g_ovf_n, 1);
        if (o < OVF_MAX) g_ovf[o] = make_int4(s, d, vbits, 0);
    }
}

__global__ void fill_bucket_kernel(const void* __restrict__ src, const void* __restrict__ dst,
                                   const float* __restrict__ val, int n_edges) {
    const bool is64 = (g_is64 != 0);
    int nq = n_edges >> 2;
    int stride = gridDim.x * blockDim.x;
    int tid0 = blockIdx.x * blockDim.x + threadIdx.x;
    for (int q = tid0; q < nq; q += stride) {
        int4   d = load_idx4(dst, q, is64);
        int4   s = load_idx4(src, q, is64);
        float4 v = ((const float4*)val)[q];
        bucket_put(d.x, s.x, __float_as_int(v.x));
        bucket_put(d.y, s.y, __float_as_int(v.y));
        bucket_put(d.z, s.z, __float_as_int(v.z));
        bucket_put(d.w, s.w, __float_as_int(v.w));
    }
    int t0 = nq << 2;
    int r = n_edges - t0;
    if (tid0 < r) {
        int e = t0 + tid0;
        bucket_put(load_idx(dst, e, is64), load_idx(src, e, is64),
                   __float_as_int(val[e]));
    }
}

// Overflow fix-up (exact) for layers 1-2: y[d] += v * x[s]. One warp/edge.
__global__ void ovf_add_kernel(int sel) {
    const __half2* __restrict__ x = sel ? h_bufB : h_bufA;
    __half2*       __restrict__ y = sel ? h_bufA : h_bufB;
    int n = g_ovf_n; if (n > OVF_MAX) n = OVF_MAX;
    int nw = (gridDim.x * blockDim.x) >> 5;
    int w  = (blockIdx.x * blockDim.x + threadIdx.x) >> 5;
    int lane = threadIdx.x & 31;
    for (int i = w; i < n; i += nw) {
        int4 e = g_ovf[i];
        float v = __int_as_float(e.z);
        float2 xf = __half22float2(x[(size_t)e.x * DIM2 + lane]);
        atomicAdd(&y[(size_t)e.y * DIM2 + lane], __floats2half2_rn(v * xf.x, v * xf.y));
    }
}

__global__ void ovf_add_l3_kernel() {
    int n = g_ovf_n; if (n > OVF_MAX) n = OVF_MAX;
    int nw = (gridDim.x * blockDim.x) >> 5;
    int w  = (blockIdx.x * blockDim.x + threadIdx.x) >> 5;
    int lane = threadIdx.x & 31;
    for (int i = w; i < n; i += nw) {
        int4 e = g_ovf[i];
        if (!g_flag[e.y]) continue;
        float v = __int_as_float(e.z);
        float2 xf = __half22float2(h_bufA[(size_t)e.x * DIM2 + lane]);
        float* yp = g_l3 + (size_t)e.y * DIM + lane * 2;
        atomicAdd(yp,     v * xf.x);
        atomicAdd(yp + 1, v * xf.y);
    }
}

// ======== FALLBACK PATH (exact int2 CSR): hist + scan + cursor fill ========
__global__ void hist_kernel(const void* __restrict__ dst, int n_edges) {
    const bool is64 = (g_is64 != 0);
    int nq = n_edges >> 2;
    int stride = gridDim.x * blockDim.x;
    int tid0 = blockIdx.x * blockDim.x + threadIdx.x;
    for (int q = tid0; q < nq; q += stride) {
        int4 d = load_idx4(dst, q, is64);
        atomicAdd(&g_counts[d.x], 1);
        atomicAdd(&g_counts[d.y], 1);
        atomicAdd(&g_counts[d.z], 1);
        atomicAdd(&g_counts[d.w], 1);
    }
    int t0 = nq << 2;
    int r = n_edges - t0;
    if (tid0 < r) atomicAdd(&g_counts[load_idx(dst, t0 + tid0, is64)], 1);
}

__global__ void __launch_bounds__(SCAN_BLK)
scan_blocks_kernel(int n_nodes) {
    __shared__ int warp_tot[32];
    int tid  = threadIdx.x;
    int lane = tid & 31, wid = tid >> 5;
    int i = blockIdx.x * SCAN_BLK + tid;
    int v = (i < n_nodes) ? g_counts[i] : 0;
    int x = v;
    #pragma unroll
    for (int o = 1; o < 32; o <<= 1) {
        int t = __shfl_up_sync(0xffffffffu, x, o);
        if (lane >= o) x += t;
    }
    if (lane == 31) warp_tot[wid] = x;
    __syncthreads();
    if (wid == 0) {
        int w = warp_tot[lane];
        #pragma unroll
        for (int o = 1; o < 32; o <<= 1) {
            int t = __shfl_up_sync(0xffffffffu, w, o);
            if (lane >= o) w += t;
        }
        warp_tot[lane] = w;
    }
    __syncthreads();
    int base = wid ? warp_tot[wid - 1] : 0;
    int incl = base + x;
    if (i < n_nodes) g_counts[i] = incl - v;
    if (tid == SCAN_BLK - 1) g_part[blockIdx.x] = incl;
}

__global__ void __launch_bounds__(PARTS_MAX)
scan_parts_kernel(int nb, int n_nodes) {
    __shared__ int warp_tot[8];
    int tid = threadIdx.x, lane = tid & 31, wid = tid >> 5;
    int v = (tid < nb) ? g_part[tid] : 0;
    int x = v;
    #pragma unroll
    for (int o = 1; o < 32; o <<= 1) {
        int t = __shfl_up_sync(0xffffffffu, x, o);
        if (lane >= o) x += t;
    }
    if (lane == 31) warp_tot[wid] = x;
    __syncthreads();
    if (wid == 0 && lane < 8) {
        int w = warp_tot[lane];
        #pragma unroll
        for (int o = 1; o < 8; o <<= 1) {
            int t = __shfl_up_sync(0xffu, w, o);
            if (lane >= o) w += t;
        }
        warp_tot[lane] = w;
    }
    __syncthreads();
    int base = wid ? warp_tot[wid - 1] : 0;
    int incl = base + x;
    if (tid < nb) g_part[tid] = incl - v;
    if (tid == PARTS_MAX - 1) g_offsets[n_nodes] = incl;
}

__global__ void __launch_bounds__(SCAN_BLK)
scan_add_kernel(int n_nodes) {
    int i = blockIdx.x * SCAN_BLK + threadIdx.x;
    if (i < n_nodes) {
        int o = g_counts[i] + g_part[blockIdx.x];
        g_offsets[i] = o;
        g_cursor [i] = o;
    }
}

__global__ void fill_kernel(const void* __restrict__ src, const void* __restrict__ dst,
                            const float* __restrict__ val, int n_edges) {
    const bool is64 = (g_is64 != 0);
    int nq = n_edges >> 2;
    int stride = gridDim.x * blockDim.x;
    int tid0 = blockIdx.x * blockDim.x + threadIdx.x;
    for (int q = tid0; q < nq; q += stride) {
        int4   d = load_idx4(dst, q, is64);
        int4   s = load_idx4(src, q, is64);
        float4 v = ((const float4*)val)[q];
        int p0 = atomicAdd(&g_cursor[d.x], 1);
        int p1 = atomicAdd(&g_cursor[d.y], 1);
        int p2 = atomicAdd(&g_cursor[d.z], 1);
        int p3 = atomicAdd(&g_cursor[d.w], 1);
        g_csr[p0] = make_int2(s.x, __float_as_int(v.x));
        g_csr[p1] = make_int2(s.y, __float_as_int(v.y));
        g_csr[p2] = make_int2(s.z, __float_as_int(v.z));
        g_csr[p3] = make_int2(s.w, __float_as_int(v.w));
    }
    int t0 = nq << 2;
    int r = n_edges - t0;
    if (tid0 < r) {
        int e = t0 + tid0;
        int d = load_idx(dst, e, is64);
        int pos = atomicAdd(&g_cursor[d], 1);
        g_csr[pos] = make_int2(load_idx(src, e, is64), __float_as_int(val[e]));
    }
}

// -------- SpMM body (exact R8/R13 shape — known-good local optimum) --------
__device__ __forceinline__ float2 spmm_row(const int2* __restrict__ eb, int cnt,
                                           const __half2* __restrict__ x, int lane) {
    float2 s0 = make_float2(0.f, 0.f), s1 = make_float2(0.f, 0.f);
    int e = 0;
    for (; e + 32 <= cnt; e += 32) {
        int2 ev = eb[e + lane];
        #pragma unroll
        for (int k = 0; k < 32; k += 2) {
            int   sA = __shfl_sync(0xffffffffu, ev.x, k);
            float vA = __int_as_float(__shfl_sync(0xffffffffu, ev.y, k));
            int   sB = __shfl_sync(0xffffffffu, ev.x, k + 1);
            float vB = __int_as_float(__shfl_sync(0xffffffffu, ev.y, k + 1));
            float2 xa = __half22float2(x[sA * DIM2 + lane]);
            float2 xb = __half22float2(x[sB * DIM2 + lane]);
            s0.x += vA * xa.x; s0.y += vA * xa.y;
            s1.x += vB * xb.x; s1.y += vB * xb.y;
        }
    }
    int n = cnt - e;
    if (n > 0) {
        int2 ev = (lane < n) ? eb[e + lane] : make_int2(0, 0);
        for (int k = 0; k < n; k++) {
            int   sN = __shfl_sync(0xffffffffu, ev.x, k);
            float vN = __int_as_float(__shfl_sync(0xffffffffu, ev.y, k));
            float2 xf = __half22float2(x[sN * DIM2 + lane]);
            if (k & 1) { s1.x += vN * xf.x; s1.y += vN * xf.y; }
            else       { s0.x += vN * xf.x; s0.y += vN * xf.y; }
        }
    }
    return make_float2(s0.x + s1.x, s0.y + s1.y);
}

__device__ __forceinline__ float2 spmm_node(int node, int use_bucket,
                                            const __half2* __restrict__ x, int lane) {
    if (use_bucket) {
        int c = g_counts[node];
        if (c > CAP) c = CAP;
        return spmm_row(&g_bucket[(size_t)node * CAP], c, x, lane);
    }
    int beg = g_offsets[node];
    return spmm_row(&g_csr[beg], g_offsets[node + 1] - beg, x, lane);
}

// Layers 1-2: full graph, fp16 -> fp16. sel=0: A->B, sel=1: B->A.
__global__ void __launch_bounds__(256)
spmm_full_kernel(int sel, int use_bucket, int n_nodes) {
    const __half2* __restrict__ x = sel ? h_bufB : h_bufA;
    __half2*       __restrict__ y = sel ? h_bufA : h_bufB;
    int warp = (blockIdx.x * blockDim.x + threadIdx.x) >> 5;
    int lane = threadIdx.x & 31;
    if (warp >= n_nodes) return;
    float2 s = spmm_node(warp, use_bucket, x, lane);
    y[(size_t)warp * DIM2 + lane] = __floats2half2_rn(s.x, s.y);
}

// Layer 3: compacted queried-node list only, fp16 -> fp32 g_l3.
__global__ void __launch_bounds__(256)
spmm_last_kernel(int use_bucket) {
    int w = (blockIdx.x * blockDim.x + threadIdx.x) >> 5;
    int lane = threadIdx.x & 31;
    if (w >= g_list_n) return;
    int node = g_list[w];
    float2 s = spmm_node(node, use_bucket, h_bufA, lane);
    ((float2*)(g_l3 + (size_t)node * DIM))[lane] = s;
}

// -------- final dot: acc = e0(inputs) + l1(bufB) + l2(bufA) + l3(g_l3) -------
__global__ void dot_kernel(const void* __restrict__ users, const void* __restrict__ items,
                           const float* __restrict__ ue, const float* __restrict__ ie,
                           float* __restrict__ out, int B, int n_users) {
    const bool is64 = (g_is64 != 0);
    int warp = (blockIdx.x * blockDim.x + threadIdx.x) >> 5;
    int lane = threadIdx.x & 31;
    if (warp >= B) return;
    int u  = load_idx(users, warp, is64);
    int ni = n_users + load_idx(items, warp, is64);

    float2 e0u = ((const float2*)ue)[(size_t)u * DIM2 + lane];
    float2 l1u = __half22float2(h_bufB[(size_t)u * DIM2 + lane]);
    float2 l2u = __half22float2(h_bufA[(size_t)u * DIM2 + lane]);
    float2 l3u = ((const float2*)(g_l3 + (size_t)u * DIM))[lane];
    float ax = e0u.x + l1u.x + l2u.x + l3u.x;
    float ay = e0u.y + l1u.y + l2u.y + l3u.y;

    float2 e0i = ((const float2*)ie)[(size_t)(ni - n_users) * DIM2 + lane];
    float2 l1i = __half22float2(h_bufB[(size_t)ni * DIM2 + lane]);
    float2 l2i = __half22float2(h_bufA[(size_t)ni * DIM2 + lane]);
    float2 l3i = ((const float2*)(g_l3 + (size_t)ni * DIM))[lane];
    float bx = e0i.x + l1i.x + l2i.x + l3i.x;
    float by = e0i.y + l1i.y + l2i.y + l3i.y;

    float p = ax * bx + ay * by;
    #pragma unroll
    for (int off = 16; off > 0; off >>= 1)
        p += __shfl_xor_sync(0xffffffffu, p, off);
    if (lane == 0) out[warp] = p * (1.0f / ((N_LAYERS + 1) * (N_LAYERS + 1)));
}

extern "C" void kernel_launch(void* const* d_in, const int* in_sizes, int n_in,
                              void* d_out, int out_size) {
    // ---- resolve input permutation from size fingerprint ----
    int iu, ii, is, id, iv, iue, iie;
    if ((long long)in_sizes[0] < (long long)in_sizes[2]) {
        iu = 0; ii = 1; is = 2; id = 3; iv = 4; iue = 5; iie = 6;   // dict order
    } else {
        id = 0; is = 1; iv = 2; iie = 3; ii = 4; iue = 5; iu = 6;   // alphabetical
    }
    const void*  users    = d_in[iu];
    const void*  items    = d_in[ii];
    const void*  edge_src = d_in[is];
    const void*  edge_dst = d_in[id];
    const float* edge_val = (const float*)d_in[iv];
    const float* user_emb = (const float*)d_in[iue];
    const float* item_emb = (const float*)d_in[iie];
    float* out = (float*)d_out;

    const int B       = in_sizes[iu];
    const int n_edges = in_sizes[is];
    const int n_users = in_sizes[iue] / DIM;
    const int n_items = in_sizes[iie] / DIM;
    const int n_nodes = n_users + n_items;
    const int nU2 = n_users * DIM / 2;
    const int nT2 = n_nodes * DIM / 2;
    const int nb  = (n_nodes + SCAN_BLK - 1) / SCAN_BLK;   // <= PARTS_MAX

    const int use_bucket = ((long long)n_edges <= 80LL * n_nodes) ? 1 : 0;

    int nslots = n_edges / 2 < 4096 ? n_edges / 2 : 4096;
    detect_kernel<<<1, 1024>>>((const unsigned int*)edge_src, nslots);
    init_kernel<<<(nT2 + 255) / 256, 256>>>(user_emb, item_emb, nU2, nT2, n_nodes);
    flag_kernel<<<(B + 255) / 256, 256>>>(users, items, B, n_users);

    if (use_bucket) {
        fill_bucket_kernel<<<2048, 256>>>(edge_src, edge_dst, edge_val, n_edges);
    } else {
        hist_kernel<<<2048, 256>>>(edge_dst, n_edges);
        scan_blocks_kernel<<<nb, SCAN_BLK>>>(n_nodes);
        scan_parts_kernel<<<1, PARTS_MAX>>>(nb, n_nodes);
        scan_add_kernel<<<nb, SCAN_BLK>>>(n_nodes);
        fill_kernel<<<2048, 256>>>(edge_src, edge_dst, edge_val, n_edges);
    }

    // propagation: layers 1-2 full, layer 3 only queried nodes (compact list)
    int spmm_grid = (n_nodes * 32 + 255) / 256;
    int l3_grid   = (2 * B * 32 + 255) / 256;   // covers worst-case list size 2B
    spmm_full_kernel<<<spmm_grid, 256>>>(0, use_bucket, n_nodes);   // l1: A -> B
    if (use_bucket) ovf_add_kernel<<<16, 256>>>(0);
    spmm_full_kernel<<<spmm_grid, 256>>>(1, use_bucket, n_nodes);   // l2: B -> A
    if (use_bucket) ovf_add_kernel<<<16, 256>>>(1);
    spmm_last_kernel<<<l3_grid, 256>>>(use_bucket);                 // l3: A -> g_l3
    if (use_bucket) ovf_add_l3_kernel<<<16, 256>>>();

    // final dots (acc assembled in-kernel)
    dot_kernel<<<(B * 32 + 255) / 256, 256>>>(users, items, user_emb, item_emb,
                                              out, B, n_users);
}

// round 17
// speedup vs baseline: 1.1304x; 1.0105x over previous
#include <cuda_runtime.h>
#include <cuda_fp16.h>

#define DIM 64
#define DIM2 (DIM / 2)
#define N_LAYERS 3
#define NODES_MAX 262144
#define EDGES_MAX 16000000
#define CAP 96             // bucket capacity (mean degree guard: <=80)
#define OVF_MAX 1048576
#define SCAN_BLK 1024
#define PARTS_MAX 256      // NODES_MAX / SCAN_BLK

// -------- static device scratch (no allocations allowed) --------
// Referenced ONLY from device code (host-side symbol decay = ATS-backed
// host shadow on GB300 — the silent R2-R4 bug).
__device__ int     g_is64;
__device__ int     g_ovf_n;
__device__ int     g_list_n;
__device__ int     g_counts [NODES_MAX];
__device__ int     g_part   [PARTS_MAX];
__device__ int     g_offsets[NODES_MAX + 1];
__device__ int     g_cursor [NODES_MAX];
__device__ int     g_flag   [NODES_MAX];
__device__ int     g_list   [NODES_MAX];            // unique queried nodes
__device__ int2    g_csr    [EDGES_MAX];            // fallback CSR (exact)
__device__ int2    g_bucket [(size_t)NODES_MAX * CAP];  // primary: int2 bucket CSR
__device__ int4    g_ovf    [OVF_MAX];              // exact (src, dst, val_bits)
__device__ __half2 h_bufA   [NODES_MAX * DIM2];     // e0 -> layer-2 output
__device__ __half2 h_bufB   [NODES_MAX * DIM2];     // layer-1 output
__device__ float   g_l3     [NODES_MAX * DIM];      // layer-3 output (queried rows)

// -------- index loads: int32 or int64 --------
__device__ __forceinline__ int load_idx(const void* p, int i, bool is64) {
    if (is64) return (int)((const long long*)p)[i];
    return ((const int*)p)[i];
}
__device__ __forceinline__ int4 load_idx4(const void* p, int q, bool is64) {
    if (is64) {
        longlong2 a = __ldcs((const longlong2*)p + 2 * q);
        longlong2 b = __ldcs((const longlong2*)p + 2 * q + 1);
        return make_int4((int)a.x, (int)a.y, (int)b.x, (int)b.y);
    }
    return __ldcs((const int4*)p + q);
}

// -------- dtype detection: odd 32-bit words all zero => int64 --------
__global__ void detect_kernel(const unsigned int* __restrict__ p, int nslots) {
    __shared__ unsigned int acc;
    if (threadIdx.x == 0) acc = 0u;
    __syncthreads();
    unsigned int v = 0u;
    for (int s = threadIdx.x; s < nslots; s += 1024) v |= p[2 * s + 1];
    if (v) atomicOr(&acc, 1u);
    __syncthreads();
    if (threadIdx.x == 0) g_is64 = (acc == 0u) ? 1 : 0;
}

// -------- init (fused): h_bufA = fp16(emb); counts/flag = 0; queried list ----
__global__ void init_kernel(const float* __restrict__ ue, const float* __restrict__ ie,
                            const void* __restrict__ users, const void* __restrict__ items,
                            int nU2, int nT2, int n_nodes, int B, int n_users) {
    int i = blockIdx.x * blockDim.x + threadIdx.x;
    if (i == 0) { g_ovf_n = 0; g_list_n = 0; }
    if (i < nT2) {
        float2 v = (i < nU2) ? ((const float2*)ue)[i] : ((const float2*)ie)[i - nU2];
        h_bufA[i] = __floats2half2_rn(v.x, v.y);
    }
    if (i < n_nodes) { g_counts[i] = 0; g_flag[i] = 0; }
}

// flag must run after all g_flag zeroing completes -> separate tiny kernel
__global__ void flag_kernel(const void* __restrict__ users, const void* __restrict__ items,
                            int B, int n_users) {
    const bool is64 = (g_is64 != 0);
    int i = blockIdx.x * blockDim.x + threadIdx.x;
    if (i < B) {
        int u = load_idx(users, i, is64);
        if (atomicExch(&g_flag[u], 1) == 0) g_list[atomicAdd(&g_list_n, 1)] = u;
        int t = n_users + load_idx(items, i, is64);
        if (atomicExch(&g_flag[t], 1) == 0) g_list[atomicAdd(&g_list_n, 1)] = t;
    }
}

// ======== PRIMARY PATH: single-pass int2 bucket fill with overflow ========
__device__ __forceinline__ void bucket_put(int d, int s, int vbits) {
    int pos = atomicAdd(&g_counts[d], 1);
    if (pos < CAP) {
        g_bucket[(size_t)d * CAP + pos] = make_int2(s, vbits);
    } else {
        int o = atomicAdd(&g_ovf_n, 1);
        if (o < OVF_MAX) g_ovf[o] = make_int4(s, d, vbits, 0);
    }
}

__global__ void fill_bucket_kernel(const void* __restrict__ src, const void* __restrict__ dst,
                                   const float* __restrict__ val, int n_edges) {
    const bool is64 = (g_is64 != 0);
    int nq = n_edges >> 2;
    int stride = gridDim.x * blockDim.x;
    int tid0 = blockIdx.x * blockDim.x + threadIdx.x;
    for (int q = tid0; q < nq; q += stride) {
        int4   d = load_idx4(dst, q, is64);
        int4   s = load_idx4(src, q, is64);
        float4 v = __ldcs((const float4*)val + q);
        bucket_put(d.x, s.x, __float_as_int(v.x));
        bucket_put(d.y, s.y, __float_as_int(v.y));
        bucket_put(d.z, s.z, __float_as_int(v.z));
        bucket_put(d.w, s.w, __float_as_int(v.w));
    }
    int t0 = nq << 2;
    int r = n_edges - t0;
    if (tid0 < r) {
        int e = t0 + tid0;
        bucket_put(load_idx(dst, e, is64), load_idx(src, e, is64),
                   __float_as_int(val[e]));
    }
}

// Overflow fix-up (exact) for layers 1-2: y[d] += v * x[s]. One warp/edge.
__global__ void ovf_add_kernel(int sel) {
    const __half2* __restrict__ x = sel ? h_bufB : h_bufA;
    __half2*       __restrict__ y = sel ? h_bufA : h_bufB;
    int n = g_ovf_n; if (n > OVF_MAX) n = OVF_MAX;
    int nw = (gridDim.x * blockDim.x) >> 5;
    int w  = (blockIdx.x * blockDim.x + threadIdx.x) >> 5;
    int lane = threadIdx.x & 31;
    for (int i = w; i < n; i += nw) {
        int4 e = g_ovf[i];
        float v = __int_as_float(e.z);
        float2 xf = __half22float2(x[(size_t)e.x * DIM2 + lane]);
        atomicAdd(&y[(size_t)e.y * DIM2 + lane], __floats2half2_rn(v * xf.x, v * xf.y));
    }
}

__global__ void ovf_add_l3_kernel() {
    int n = g_ovf_n; if (n > OVF_MAX) n = OVF_MAX;
    int nw = (gridDim.x * blockDim.x) >> 5;
    int w  = (blockIdx.x * blockDim.x + threadIdx.x) >> 5;
    int lane = threadIdx.x & 31;
    for (int i = w; i < n; i += nw) {
        int4 e = g_ovf[i];
        if (!g_flag[e.y]) continue;
        float v = __int_as_float(e.z);
        float2 xf = __half22float2(h_bufA[(size_t)e.x * DIM2 + lane]);
        float* yp = g_l3 + (size_t)e.y * DIM + lane * 2;
        atomicAdd(yp,     v * xf.x);
        atomicAdd(yp + 1, v * xf.y);
    }
}

// ======== FALLBACK PATH (exact int2 CSR): hist + scan + cursor fill ========
__global__ void hist_kernel(const void* __restrict__ dst, int n_edges) {
    const bool is64 = (g_is64 != 0);
    int nq = n_edges >> 2;
    int stride = gridDim.x * blockDim.x;
    int tid0 = blockIdx.x * blockDim.x + threadIdx.x;
    for (int q = tid0; q < nq; q += stride) {
        int4 d = load_idx4(dst, q, is64);
        atomicAdd(&g_counts[d.x], 1);
        atomicAdd(&g_counts[d.y], 1);
        atomicAdd(&g_counts[d.z], 1);
        atomicAdd(&g_counts[d.w], 1);
    }
    int t0 = nq << 2;
    int r = n_edges - t0;
    if (tid0 < r) atomicAdd(&g_counts[load_idx(dst, t0 + tid0, is64)], 1);
}

__global__ void __launch_bounds__(SCAN_BLK)
scan_blocks_kernel(int n_nodes) {
    __shared__ int warp_tot[32];
    int tid  = threadIdx.x;
    int lane = tid & 31, wid = tid >> 5;
    int i = blockIdx.x * SCAN_BLK + tid;
    int v = (i < n_nodes) ? g_counts[i] : 0;
    int x = v;
    #pragma unroll
    for (int o = 1; o < 32; o <<= 1) {
        int t = __shfl_up_sync(0xffffffffu, x, o);
        if (lane >= o) x += t;
    }
    if (lane == 31) warp_tot[wid] = x;
    __syncthreads();
    if (wid == 0) {
        int w = warp_tot[lane];
        #pragma unroll
        for (int o = 1; o < 32; o <<= 1) {
            int t = __shfl_up_sync(0xffffffffu, w, o);
            if (lane >= o) w += t;
        }
        warp_tot[lane] = w;
    }
    __syncthreads();
    int base = wid ? warp_tot[wid - 1] : 0;
    int incl = base + x;
    if (i < n_nodes) g_counts[i] = incl - v;
    if (tid == SCAN_BLK - 1) g_part[blockIdx.x] = incl;
}

__global__ void __launch_bounds__(PARTS_MAX)
scan_parts_kernel(int nb, int n_nodes) {
    __shared__ int warp_tot[8];
    int tid = threadIdx.x, lane = tid & 31, wid = tid >> 5;
    int v = (tid < nb) ? g_part[tid] : 0;
    int x = v;
    #pragma unroll
    for (int o = 1; o < 32; o <<= 1) {
        int t = __shfl_up_sync(0xffffffffu, x, o);
        if (lane >= o) x += t;
    }
    if (lane == 31) warp_tot[wid] = x;
    __syncthreads();
    if (wid == 0 && lane < 8) {
        int w = warp_tot[lane];
        #pragma unroll
        for (int o = 1; o < 8; o <<= 1) {
            int t = __shfl_up_sync(0xffu, w, o);
            if (lane >= o) w += t;
        }
        warp_tot[lane] = w;
    }
    __syncthreads();
    int base = wid ? warp_tot[wid - 1] : 0;
    int incl = base + x;
    if (tid < nb) g_part[tid] = incl - v;
    if (tid == PARTS_MAX - 1) g_offsets[n_nodes] = incl;
}

__global__ void __launch_bounds__(SCAN_BLK)
scan_add_kernel(int n_nodes) {
    int i = blockIdx.x * SCAN_BLK + threadIdx.x;
    if (i < n_nodes) {
        int o = g_counts[i] + g_part[blockIdx.x];
        g_offsets[i] = o;
        g_cursor [i] = o;
    }
}

__global__ void fill_kernel(const void* __restrict__ src, const void* __restrict__ dst,
                            const float* __restrict__ val, int n_edges) {
    const bool is64 = (g_is64 != 0);
    int nq = n_edges >> 2;
    int stride = gridDim.x * blockDim.x;
    int tid0 = blockIdx.x * blockDim.x + threadIdx.x;
    for (int q = tid0; q < nq; q += stride) {
        int4   d = load_idx4(dst, q, is64);
        int4   s = load_idx4(src, q, is64);
        float4 v = __ldcs((const float4*)val + q);
        int p0 = atomicAdd(&g_cursor[d.x], 1);
        int p1 = atomicAdd(&g_cursor[d.y], 1);
        int p2 = atomicAdd(&g_cursor[d.z], 1);
        int p3 = atomicAdd(&g_cursor[d.w], 1);
        g_csr[p0] = make_int2(s.x, __float_as_int(v.x));
        g_csr[p1] = make_int2(s.y, __float_as_int(v.y));
        g_csr[p2] = make_int2(s.z, __float_as_int(v.z));
        g_csr[p3] = make_int2(s.w, __float_as_int(v.w));
    }
    int t0 = nq << 2;
    int r = n_edges - t0;
    if (tid0 < r) {
        int e = t0 + tid0;
        int d = load_idx(dst, e, is64);
        int pos = atomicAdd(&g_cursor[d], 1);
        g_csr[pos] = make_int2(load_idx(src, e, is64), __float_as_int(val[e]));
    }
}

// -------- SpMM body (exact R8/R13 shape — known-good local optimum) --------
__device__ __forceinline__ float2 spmm_row(const int2* __restrict__ eb, int cnt,
                                           const __half2* __restrict__ x, int lane) {
    float2 s0 = make_float2(0.f, 0.f), s1 = make_float2(0.f, 0.f);
    int e = 0;
    for (; e + 32 <= cnt; e += 32) {
        int2 ev = eb[e + lane];
        #pragma unroll
        for (int k = 0; k < 32; k += 2) {
            int   sA = __shfl_sync(0xffffffffu, ev.x, k);
            float vA = __int_as_float(__shfl_sync(0xffffffffu, ev.y, k));
            int   sB = __shfl_sync(0xffffffffu, ev.x, k + 1);
            float vB = __int_as_float(__shfl_sync(0xffffffffu, ev.y, k + 1));
            float2 xa = __half22float2(x[sA * DIM2 + lane]);
            float2 xb = __half22float2(x[sB * DIM2 + lane]);
            s0.x += vA * xa.x; s0.y += vA * xa.y;
            s1.x += vB * xb.x; s1.y += vB * xb.y;
        }
    }
    int n = cnt - e;
    if (n > 0) {
        int2 ev = (lane < n) ? eb[e + lane] : make_int2(0, 0);
        for (int k = 0; k < n; k++) {
            int   sN = __shfl_sync(0xffffffffu, ev.x, k);
            float vN = __int_as_float(__shfl_sync(0xffffffffu, ev.y, k));
            float2 xf = __half22float2(x[sN * DIM2 + lane]);
            if (k & 1) { s1.x += vN * xf.x; s1.y += vN * xf.y; }
            else       { s0.x += vN * xf.x; s0.y += vN * xf.y; }
        }
    }
    return make_float2(s0.x + s1.x, s0.y + s1.y);
}

__device__ __forceinline__ float2 spmm_node(int node, int use_bucket,
                                            const __half2* __restrict__ x, int lane) {
    if (use_bucket) {
        int c = g_counts[node];
        if (c > CAP) c = CAP;
        return spmm_row(&g_bucket[(size_t)node * CAP], c, x, lane);
    }
    int beg = g_offsets[node];
    return spmm_row(&g_csr[beg], g_offsets[node + 1] - beg, x, lane);
}

// Layers 1-2: full graph, fp16 -> fp16. sel=0: A->B, sel=1: B->A.
__global__ void __launch_bounds__(256)
spmm_full_kernel(int sel, int use_bucket, int n_nodes) {
    const __half2* __restrict__ x = sel ? h_bufB : h_bufA;
    __half2*       __restrict__ y = sel ? h_bufA : h_bufB;
    int warp = (blockIdx.x * blockDim.x + threadIdx.x) >> 5;
    int lane = threadIdx.x & 31;
    if (warp >= n_nodes) return;
    float2 s = spmm_node(warp, use_bucket, x, lane);
    y[(size_t)warp * DIM2 + lane] = __floats2half2_rn(s.x, s.y);
}

// Layer 3: compacted queried-node list only, fp16 -> fp32 g_l3.
__global__ void __launch_bounds__(256)
spmm_last_kernel(int use_bucket) {
    int w = (blockIdx.x * blockDim.x + threadIdx.x) >> 5;
    int lane = threadIdx.x & 31;
    if (w >= g_list_n) return;
    int node = g_list[w];
    float2 s = spmm_node(node, use_bucket, h_bufA, lane);
    ((float2*)(g_l3 + (size_t)node * DIM))[lane] = s;
}

// -------- final dot: acc = e0(inputs) + l1(bufB) + l2(bufA) + l3(g_l3) -------
__global__ void dot_kernel(const void* __restrict__ users, const void* __restrict__ items,
                           const float* __restrict__ ue, const float* __restrict__ ie,
                           float* __restrict__ out, int B, int n_users) {
    const bool is64 = (g_is64 != 0);
    int warp = (blockIdx.x * blockDim.x + threadIdx.x) >> 5;
    int lane = threadIdx.x & 31;
    if (warp >= B) return;
    int u  = load_idx(users, warp, is64);
    int ni = n_users + load_idx(items, warp, is64);

    float2 e0u = ((const float2*)ue)[(size_t)u * DIM2 + lane];
    float2 l1u = __half22float2(h_bufB[(size_t)u * DIM2 + lane]);
    float2 l2u = __half22float2(h_bufA[(size_t)u * DIM2 + lane]);
    float2 l3u = ((const float2*)(g_l3 + (size_t)u * DIM))[lane];
    float ax = e0u.x + l1u.x + l2u.x + l3u.x;
    float ay = e0u.y + l1u.y + l2u.y + l3u.y;

    float2 e0i = ((const float2*)ie)[(size_t)(ni - n_users) * DIM2 + lane];
    float2 l1i = __half22float2(h_bufB[(size_t)ni * DIM2 + lane]);
    float2 l2i = __half22float2(h_bufA[(size_t)ni * DIM2 + lane]);
    float2 l3i = ((const float2*)(g_l3 + (size_t)ni * DIM))[lane];
    float bx = e0i.x + l1i.x + l2i.x + l3i.x;
    float by = e0i.y + l1i.y + l2i.y + l3i.y;

    float p = ax * bx + ay * by;
    #pragma unroll
    for (int off = 16; off > 0; off >>= 1)
        p += __shfl_xor_sync(0xffffffffu, p, off);
    if (lane == 0) out[warp] = p * (1.0f / ((N_LAYERS + 1) * (N_LAYERS + 1)));
}

extern "C" void kernel_launch(void* const* d_in, const int* in_sizes, int n_in,
                              void* d_out, int out_size) {
    // ---- resolve input permutation from size fingerprint ----
    int iu, ii, is, id, iv, iue, iie;
    if ((long long)in_sizes[0] < (long long)in_sizes[2]) {
        iu = 0; ii = 1; is = 2; id = 3; iv = 4; iue = 5; iie = 6;   // dict order
    } else {
        id = 0; is = 1; iv = 2; iie = 3; ii = 4; iue = 5; iu = 6;   // alphabetical
    }
    const void*  users    = d_in[iu];
    const void*  items    = d_in[ii];
    const void*  edge_src = d_in[is];
    const void*  edge_dst = d_in[id];
    const float* edge_val = (const float*)d_in[iv];
    const float* user_emb = (const float*)d_in[iue];
    const float* item_emb = (const float*)d_in[iie];
    float* out = (float*)d_out;

    const int B       = in_sizes[iu];
    const int n_edges = in_sizes[is];
    const int n_users = in_sizes[iue] / DIM;
    const int n_items = in_sizes[iie] / DIM;
    const int n_nodes = n_users + n_items;
    const int nU2 = n_users * DIM / 2;
    const int nT2 = n_nodes * DIM / 2;
    const int nb  = (n_nodes + SCAN_BLK - 1) / SCAN_BLK;   // <= PARTS_MAX

    const int use_bucket = ((long long)n_edges <= 80LL * n_nodes) ? 1 : 0;

    int nslots = n_edges / 2 < 4096 ? n_edges / 2 : 4096;
    detect_kernel<<<1, 1024>>>((const unsigned int*)edge_src, nslots);
    init_kernel<<<(nT2 + 255) / 256, 256>>>(user_emb, item_emb, users, items,
                                            nU2, nT2, n_nodes, B, n_users);
    flag_kernel<<<(B + 255) / 256, 256>>>(users, items, B, n_users);

    if (use_bucket) {
        fill_bucket_kernel<<<2048, 256>>>(edge_src, edge_dst, edge_val, n_edges);
    } else {
        hist_kernel<<<2048, 256>>>(edge_dst, n_edges);
        scan_blocks_kernel<<<nb, SCAN_BLK>>>(n_nodes);
        scan_parts_kernel<<<1, PARTS_MAX>>>(nb, n_nodes);
        scan_add_kernel<<<nb, SCAN_BLK>>>(n_nodes);
        fill_kernel<<<2048, 256>>>(edge_src, edge_dst, edge_val, n_edges);
    }

    // propagation: layers 1-2 full, layer 3 only queried nodes (compact list)
    int spmm_grid = (n_nodes * 32 + 255) / 256;
    int l3_grid   = (2 * B * 32 + 255) / 256;   // covers worst-case list size 2B
    spmm_full_kernel<<<spmm_grid, 256>>>(0, use_bucket, n_nodes);   // l1: A -> B
    if (use_bucket) ovf_add_kernel<<<16, 256>>>(0);
    spmm_full_kernel<<<spmm_grid, 256>>>(1, use_bucket, n_nodes);   // l2: B -> A
    if (use_bucket) ovf_add_kernel<<<16, 256>>>(1);
    spmm_last_kernel<<<l3_grid, 256>>>(use_bucket);                 // l3: A -> g_l3
    if (use_bucket) ovf_add_l3_kernel<<<16, 256>>>();

    // final dots (acc assembled in-kernel)
    dot_kernel<<<(B * 32 + 255) / 256, 256>>>(users, items, user_emb, item_emb,
                                              out, B, n_users);
}